// round 12
// baseline (speedup 1.0000x reference)
#include <cuda_runtime.h>
#include <cstdint>

// Problem constants
#define Bn 16
#define Cn 256
#define Hn 128
#define Wn 128
#define HW 16384              // 2^14
#define HW4 4096
#define CHW4 1048576          // 2^20
#define BHW (Bn*HW)           // 262144
#define BHW4 (BHW/4)          // 65536
#define TOTAL4 (Bn*CHW4)      // 16777216

// Scratch
__device__ float g_s[BHW];    // channel sums, 1 MiB
__device__ float g_x1[BHW];   // conv result, 1 MiB

// ---------------------------------------------------------------------------
// K1: s[b,hw] = sum_c x[b,c,hw], block-level reduction (R10 proven: 6.57TB/s).
// 4096 blocks x 256 threads; thread (cg,px4) sums 16 channels; SMEM combine.
// ---------------------------------------------------------------------------
__global__ void __launch_bounds__(256) reduce_s_kernel(const float4* __restrict__ x,
                                                       float4* __restrict__ s4) {
    __shared__ float4 aux[256];          // [cg][px4]

    const int tid = threadIdx.x;
    const int px4 = tid & 15;
    const int cg  = tid >> 4;
    const int blk = blockIdx.x;          // 0..4095
    const int b   = blk >> 8;
    const int p0  = (blk & 255) * 16 + px4;

    const float4* p = x + (size_t)b * CHW4 + (size_t)cg * 16 * HW4 + p0;

    float4 acc = make_float4(0.f, 0.f, 0.f, 0.f);
#pragma unroll
    for (int c = 0; c < 16; ++c) {
        float4 v = p[(size_t)c * HW4];
        acc.x += v.x; acc.y += v.y; acc.z += v.z; acc.w += v.w;
    }
    aux[tid] = acc;
    __syncthreads();

    if (tid < 16) {
        float4 a = aux[tid];
#pragma unroll
        for (int g = 1; g < 16; ++g) {
            float4 v = aux[g * 16 + tid];
            a.x += v.x; a.y += v.y; a.z += v.z; a.w += v.w;
        }
        s4[(size_t)b * HW4 + (blk & 255) * 16 + tid] = a;
    }
}

// ---------------------------------------------------------------------------
// K2: x1 = conv3x3(s), zero pad, cross-correlation. float4-vectorized:
// 65536 threads, each computes 4 contiguous output pixels of one row.
// ---------------------------------------------------------------------------
__global__ void __launch_bounds__(256) conv3_kernel(const float* __restrict__ s,
                                                    const float* __restrict__ f,
                                                    float4* __restrict__ x1_4) {
    int j = blockIdx.x * blockDim.x + threadIdx.x;  // 0 .. BHW4-1
    int b   = j >> 12;                  // HW4 = 4096 per batch
    int hw4 = j & 4095;
    int h   = hw4 >> 5;                 // 32 float4 per row
    int w0  = (hw4 & 31) * 4;           // first pixel column (0,4,...,124)

    float fw[9];
#pragma unroll
    for (int k = 0; k < 9; ++k) fw[k] = f[k];

    const float* sb = s + b * HW;
    float o[4] = {0.f, 0.f, 0.f, 0.f};

#pragma unroll
    for (int di = 0; di < 3; ++di) {
        int hh = h + di - 1;
        if (hh < 0 || hh >= Hn) continue;
        const float* row = sb + hh * Wn;
        // load the 6 floats covering columns w0-1 .. w0+4 (with zero pad)
        float rv[6];
#pragma unroll
        for (int k = 0; k < 6; ++k) {
            int ww = w0 - 1 + k;
            rv[k] = (ww >= 0 && ww < Wn) ? row[ww] : 0.f;
        }
#pragma unroll
        for (int pi = 0; pi < 4; ++pi) {
            o[pi] += rv[pi]     * fw[di * 3 + 0];
            o[pi] += rv[pi + 1] * fw[di * 3 + 1];
            o[pi] += rv[pi + 2] * fw[di * 3 + 2];
        }
    }
    x1_4[j] = make_float4(o[0], o[1], o[2], o[3]);
}

// ---------------------------------------------------------------------------
// K3: out = x - x1 (broadcast over C), ILP=4.
// 4194304 threads; each handles float4 elements i, i+S, i+2S, i+3S.
// ---------------------------------------------------------------------------
#define S4 (TOTAL4 / 4)       // 4194304

__global__ void __launch_bounds__(256) sub_kernel(const float4* __restrict__ x,
                                                  const float4* __restrict__ x1,
                                                  float4* __restrict__ out) {
    int i = blockIdx.x * blockDim.x + threadIdx.x;  // 0 .. S4-1

    float4 xv[4], bv[4];
#pragma unroll
    for (int k = 0; k < 4; ++k) {
        int idx = i + k * S4;
        xv[k] = x[idx];
        bv[k] = __ldg(&x1[((idx >> 20) << 12) + (idx & 4095)]);
    }
#pragma unroll
    for (int k = 0; k < 4; ++k) {
        int idx = i + k * S4;
        float4 o;
        o.x = xv[k].x - bv[k].x; o.y = xv[k].y - bv[k].y;
        o.z = xv[k].z - bv[k].z; o.w = xv[k].w - bv[k].w;
        out[idx] = o;
    }
}

// ---------------------------------------------------------------------------
extern "C" void kernel_launch(void* const* d_in, const int* in_sizes, int n_in,
                              void* d_out, int out_size) {
    const float* x = (const float*)d_in[0];   // (16,256,128,128) fp32
    const float* f = (const float*)d_in[1];   // (3,3) fp32
    float* out = (float*)d_out;

    static float* s_ptr  = nullptr;
    static float* x1_ptr = nullptr;
    if (s_ptr == nullptr) {
        cudaGetSymbolAddress((void**)&s_ptr,  g_s);
        cudaGetSymbolAddress((void**)&x1_ptr, g_x1);
    }

    // K1: channel sums (reads 256 MiB, writes 1 MiB)
    reduce_s_kernel<<<4096, 256>>>((const float4*)x, (float4*)s_ptr);

    // K2: conv3x3 (L2-resident, float4-vectorized)
    conv3_kernel<<<BHW4 / 256, 256>>>(s_ptr, f, (float4*)x1_ptr);

    // K3: broadcast subtract, ILP=4 (reads 256 MiB + 1 MiB, writes 256 MiB)
    sub_kernel<<<S4 / 256, 256>>>(
        (const float4*)x, (const float4*)x1_ptr, (float4*)out);
}

// round 13
// speedup vs baseline: 1.0039x; 1.0039x over previous
#include <cuda_runtime.h>
#include <cstdint>

// Problem constants
#define Bn 16
#define Cn 256
#define Hn 128
#define Wn 128
#define HW 16384              // 2^14
#define HW4 4096
#define CHW4 1048576          // 2^20
#define BHW (Bn*HW)           // 262144
#define BHW4 (BHW/4)          // 65536
#define TOTAL4 (Bn*CHW4)      // 16777216

// Scratch
__device__ float g_s[BHW];    // channel sums, 1 MiB
__device__ float g_x1[BHW];   // conv result, 1 MiB

// ---------------------------------------------------------------------------
// K1: s[b,hw] = sum_c x[b,c,hw], block-level reduction (R10 exact: 6.57 TB/s).
// 4096 blocks x 256 threads; thread (cg,px4) sums 16 channels; SMEM combine.
// ---------------------------------------------------------------------------
__global__ void __launch_bounds__(256) reduce_s_kernel(const float4* __restrict__ x,
                                                       float4* __restrict__ s4) {
    __shared__ float4 aux[256];          // [cg][px4]

    const int tid = threadIdx.x;
    const int px4 = tid & 15;
    const int cg  = tid >> 4;
    const int blk = blockIdx.x;          // 0..4095
    const int b   = blk >> 8;
    const int p0  = (blk & 255) * 16 + px4;

    const float4* p = x + (size_t)b * CHW4 + (size_t)cg * 16 * HW4 + p0;

    float4 acc = make_float4(0.f, 0.f, 0.f, 0.f);
#pragma unroll
    for (int c = 0; c < 16; ++c) {
        float4 v = p[(size_t)c * HW4];
        acc.x += v.x; acc.y += v.y; acc.z += v.z; acc.w += v.w;
    }
    aux[tid] = acc;
    __syncthreads();

    if (tid < 16) {
        float4 a = aux[tid];
#pragma unroll
        for (int g = 1; g < 16; ++g) {
            float4 v = aux[g * 16 + tid];
            a.x += v.x; a.y += v.y; a.z += v.z; a.w += v.w;
        }
        s4[(size_t)b * HW4 + (blk & 255) * 16 + tid] = a;
    }
}

// ---------------------------------------------------------------------------
// K2: x1 = conv3x3(s), zero pad, cross-correlation. float4-vectorized (R12).
// 65536 threads, each computes 4 contiguous output pixels of one row.
// ---------------------------------------------------------------------------
__global__ void __launch_bounds__(256) conv3_kernel(const float* __restrict__ s,
                                                    const float* __restrict__ f,
                                                    float4* __restrict__ x1_4) {
    int j = blockIdx.x * blockDim.x + threadIdx.x;  // 0 .. BHW4-1
    int b   = j >> 12;                  // HW4 = 4096 per batch
    int hw4 = j & 4095;
    int h   = hw4 >> 5;                 // 32 float4 per row
    int w0  = (hw4 & 31) * 4;           // first pixel column

    float fw[9];
#pragma unroll
    for (int k = 0; k < 9; ++k) fw[k] = f[k];

    const float* sb = s + b * HW;
    float o[4] = {0.f, 0.f, 0.f, 0.f};

#pragma unroll
    for (int di = 0; di < 3; ++di) {
        int hh = h + di - 1;
        if (hh < 0 || hh >= Hn) continue;
        const float* row = sb + hh * Wn;
        float rv[6];
#pragma unroll
        for (int k = 0; k < 6; ++k) {
            int ww = w0 - 1 + k;
            rv[k] = (ww >= 0 && ww < Wn) ? row[ww] : 0.f;
        }
#pragma unroll
        for (int pi = 0; pi < 4; ++pi) {
            o[pi] += rv[pi]     * fw[di * 3 + 0];
            o[pi] += rv[pi + 1] * fw[di * 3 + 1];
            o[pi] += rv[pi + 2] * fw[di * 3 + 2];
        }
    }
    x1_4[j] = make_float4(o[0], o[1], o[2], o[3]);
}

// ---------------------------------------------------------------------------
// K3: out = x - x1 (broadcast over C), ILP=2 (R5 exact: 75.0µs measured).
// 8388608 threads; each handles float4 elements i and i+TOTAL4/2.
// ---------------------------------------------------------------------------
__global__ void __launch_bounds__(256) sub_kernel(const float4* __restrict__ x,
                                                  const float4* __restrict__ x1,
                                                  float4* __restrict__ out) {
    int i = blockIdx.x * blockDim.x + threadIdx.x;  // 0 .. 8388607
    int i2 = i + (TOTAL4 / 2);

    float4 xa = x[i];
    float4 xb = x[i2];
    float4 ba = __ldg(&x1[((i  >> 20) << 12) + (i  & 4095)]);
    float4 bb = __ldg(&x1[((i2 >> 20) << 12) + (i2 & 4095)]);

    float4 oa, ob;
    oa.x = xa.x - ba.x; oa.y = xa.y - ba.y; oa.z = xa.z - ba.z; oa.w = xa.w - ba.w;
    ob.x = xb.x - bb.x; ob.y = xb.y - bb.y; ob.z = xb.z - bb.z; ob.w = xb.w - bb.w;
    out[i]  = oa;
    out[i2] = ob;
}

// ---------------------------------------------------------------------------
extern "C" void kernel_launch(void* const* d_in, const int* in_sizes, int n_in,
                              void* d_out, int out_size) {
    const float* x = (const float*)d_in[0];   // (16,256,128,128) fp32
    const float* f = (const float*)d_in[1];   // (3,3) fp32
    float* out = (float*)d_out;

    static float* s_ptr  = nullptr;
    static float* x1_ptr = nullptr;
    if (s_ptr == nullptr) {
        cudaGetSymbolAddress((void**)&s_ptr,  g_s);
        cudaGetSymbolAddress((void**)&x1_ptr, g_x1);
    }

    // K1: channel sums (reads 256 MiB, writes 1 MiB)
    reduce_s_kernel<<<4096, 256>>>((const float4*)x, (float4*)s_ptr);

    // K2: conv3x3 (L2-resident, float4-vectorized)
    conv3_kernel<<<BHW4 / 256, 256>>>(s_ptr, f, (float4*)x1_ptr);

    // K3: broadcast subtract, ILP=2 (reads 256 MiB + 1 MiB, writes 256 MiB)
    sub_kernel<<<(TOTAL4 / 2) / 256, 256>>>(
        (const float4*)x, (const float4*)x1_ptr, (float4*)out);
}

// round 14
// speedup vs baseline: 1.0042x; 1.0002x over previous
#include <cuda_runtime.h>
#include <cstdint>

// Problem constants
#define Bn 16
#define Cn 256
#define Hn 128
#define Wn 128
#define HW 16384              // 2^14
#define HW4 4096
#define CHW4 1048576          // 2^20
#define BH 8                  // batches per half
#define HALF4 (BH*CHW4)       // 8388608 float4 per half
#define HHW (BH*HW)           // 131072 pixels per half
#define HHW4 (HHW/4)          // 32768

// Scratch: separate buffers per half (chains fully independent)
__device__ float g_s[2][HHW];    // channel sums
__device__ float g_x1[2][HHW];   // conv results

// ---------------------------------------------------------------------------
// K1: s[b,hw] = sum_c x[b,c,hw] for one half (R10-proven config).
// 2048 blocks x 256 threads; thread (cg,px4) sums 16 channels; SMEM combine.
// ---------------------------------------------------------------------------
__global__ void __launch_bounds__(256) reduce_s_kernel(const float4* __restrict__ x,
                                                       float4* __restrict__ s4) {
    __shared__ float4 aux[256];

    const int tid = threadIdx.x;
    const int px4 = tid & 15;
    const int cg  = tid >> 4;
    const int blk = blockIdx.x;          // 0..2047
    const int b   = blk >> 8;            // 0..7 (batch in half)
    const int p0  = (blk & 255) * 16 + px4;

    const float4* p = x + (size_t)b * CHW4 + (size_t)cg * 16 * HW4 + p0;

    float4 acc = make_float4(0.f, 0.f, 0.f, 0.f);
#pragma unroll
    for (int c = 0; c < 16; ++c) {
        float4 v = p[(size_t)c * HW4];
        acc.x += v.x; acc.y += v.y; acc.z += v.z; acc.w += v.w;
    }
    aux[tid] = acc;
    __syncthreads();

    if (tid < 16) {
        float4 a = aux[tid];
#pragma unroll
        for (int g = 1; g < 16; ++g) {
            float4 v = aux[g * 16 + tid];
            a.x += v.x; a.y += v.y; a.z += v.z; a.w += v.w;
        }
        s4[(size_t)b * HW4 + (blk & 255) * 16 + tid] = a;
    }
}

// ---------------------------------------------------------------------------
// K2: x1 = conv3x3(s) for one half, float4-vectorized (R12 variant).
// 32768 float4 outputs.
// ---------------------------------------------------------------------------
__global__ void __launch_bounds__(256) conv3_kernel(const float* __restrict__ s,
                                                    const float* __restrict__ f,
                                                    float4* __restrict__ x1_4) {
    int j = blockIdx.x * blockDim.x + threadIdx.x;  // 0 .. HHW4-1
    int b   = j >> 12;                  // 0..7
    int hw4 = j & 4095;
    int h   = hw4 >> 5;
    int w0  = (hw4 & 31) * 4;

    float fw[9];
#pragma unroll
    for (int k = 0; k < 9; ++k) fw[k] = f[k];

    const float* sb = s + b * HW;
    float o[4] = {0.f, 0.f, 0.f, 0.f};

#pragma unroll
    for (int di = 0; di < 3; ++di) {
        int hh = h + di - 1;
        if (hh < 0 || hh >= Hn) continue;
        const float* row = sb + hh * Wn;
        float rv[6];
#pragma unroll
        for (int k = 0; k < 6; ++k) {
            int ww = w0 - 1 + k;
            rv[k] = (ww >= 0 && ww < Wn) ? row[ww] : 0.f;
        }
#pragma unroll
        for (int pi = 0; pi < 4; ++pi) {
            o[pi] += rv[pi]     * fw[di * 3 + 0];
            o[pi] += rv[pi + 1] * fw[di * 3 + 1];
            o[pi] += rv[pi + 2] * fw[di * 3 + 2];
        }
    }
    x1_4[j] = make_float4(o[0], o[1], o[2], o[3]);
}

// ---------------------------------------------------------------------------
// K3: out = x - x1 for one half, ILP=2 (R5-proven config).
// 4194304 threads; elements i and i+HALF4/2.
// ---------------------------------------------------------------------------
__global__ void __launch_bounds__(256) sub_kernel(const float4* __restrict__ x,
                                                  const float4* __restrict__ x1,
                                                  float4* __restrict__ out) {
    int i = blockIdx.x * blockDim.x + threadIdx.x;  // 0 .. HALF4/2-1
    int i2 = i + (HALF4 / 2);

    float4 xa = x[i];
    float4 xb = x[i2];
    float4 ba = __ldg(&x1[((i  >> 20) << 12) + (i  & 4095)]);
    float4 bb = __ldg(&x1[((i2 >> 20) << 12) + (i2 & 4095)]);

    float4 oa, ob;
    oa.x = xa.x - ba.x; oa.y = xa.y - ba.y; oa.z = xa.z - ba.z; oa.w = xa.w - ba.w;
    ob.x = xb.x - bb.x; ob.y = xb.y - bb.y; ob.z = xb.z - bb.z; ob.w = xb.w - bb.w;
    out[i]  = oa;
    out[i2] = ob;
}

// ---------------------------------------------------------------------------
extern "C" void kernel_launch(void* const* d_in, const int* in_sizes, int n_in,
                              void* d_out, int out_size) {
    const float* x = (const float*)d_in[0];   // (16,256,128,128) fp32
    const float* f = (const float*)d_in[1];   // (3,3) fp32
    float* out = (float*)d_out;

    static float* s_ptr  = nullptr;
    static float* x1_ptr = nullptr;
    static cudaStream_t st[2];
    static cudaEvent_t  e_fork, e_join[2];
    if (s_ptr == nullptr) {
        // First call is the (uncaptured) correctness run: safe to create here.
        cudaGetSymbolAddress((void**)&s_ptr,  g_s);
        cudaGetSymbolAddress((void**)&x1_ptr, g_x1);
        cudaStreamCreateWithFlags(&st[0], cudaStreamNonBlocking);
        cudaStreamCreateWithFlags(&st[1], cudaStreamNonBlocking);
        cudaEventCreateWithFlags(&e_fork,    cudaEventDisableTiming);
        cudaEventCreateWithFlags(&e_join[0], cudaEventDisableTiming);
        cudaEventCreateWithFlags(&e_join[1], cudaEventDisableTiming);
    }

    // Fork from the (captured) legacy stream
    cudaEventRecord(e_fork, 0);
    cudaStreamWaitEvent(st[0], e_fork, 0);
    cudaStreamWaitEvent(st[1], e_fork, 0);

    for (int h = 0; h < 2; ++h) {
        const float4* xh = (const float4*)x + (size_t)h * HALF4;
        float4*       oh = (float4*)out     + (size_t)h * HALF4;
        float* sh  = s_ptr  + (size_t)h * HHW;
        float* x1h = x1_ptr + (size_t)h * HHW;

        reduce_s_kernel<<<2048, 256, 0, st[h]>>>(xh, (float4*)sh);
        conv3_kernel<<<HHW4 / 256, 256, 0, st[h]>>>(sh, f, (float4*)x1h);
        sub_kernel<<<(HALF4 / 2) / 256, 256, 0, st[h]>>>(
            xh, (const float4*)x1h, oh);

        cudaEventRecord(e_join[h], st[h]);
    }

    // Join back to the legacy stream
    cudaStreamWaitEvent(0, e_join[0], 0);
    cudaStreamWaitEvent(0, e_join[1], 0);
}